// round 8
// baseline (speedup 1.0000x reference)
#include <cuda_runtime.h>
#include <math.h>

// ClusteredAttention: b=4, l=4096, d=64 fp32, labels in [0,8).
// Counting-sort by label -> perm/slab/block-table; gather K/V cluster-
// contiguous; flash-attend cluster-aligned 64-query blocks (256 thr, 4x4
// register tiles; Q gathered in-kernel via perm; vectorized K/V tile loads).
// Time-query split-softmax chunks absorbed into spare grid slots; fast
// combine kernel last. Serial latency chains (is64 detect, combine loads)
// parallelized.

#define LSEQ 4096
#define LM1  4095
#define HD   64
#define BM   64
#define BN   64
#define PAD  65
#define NTHREADS 256
#define MAXB 4
#define MAXBLK 72
#define TQ_CHUNKS 256
#define TQ_NCH    (LSEQ / TQ_CHUNKS)   // 16
#define GRIDX     (MAXBLK + TQ_NCH)    // 88

__device__ float g_Ks[MAXB * LSEQ * HD];
__device__ float g_Vs[MAXB * LSEQ * HD];
__device__ int   g_perm[MAXB * LSEQ];
__device__ int   g_slab[MAXB * LSEQ];
__device__ int4  g_btab[MAXB * MAXBLK];
__device__ int   g_nblk[MAXB];
__device__ float g_tq[MAXB * TQ_NCH * (HD + 2)];

// ---------------------------------------------------------------------------
// Kernel A: stable counting sort by label + cluster-aligned block table.
// ---------------------------------------------------------------------------
__global__ void sort_kernel(const int* __restrict__ lab32)
{
    __shared__ int cnt[8][256];
    __shared__ int ex[8][256];
    __shared__ int tot[8];
    __shared__ int segstart[8];
    __shared__ int sh_is64;

    const int b = blockIdx.x;
    const int tid = threadIdx.x;

    // ---- parallel int64-vs-int32 autodetect: one load per thread + ballot
    if (tid < 32) {
        int nz = (lab32[2 * tid + 1] != 0) ? 1 : 0;
        unsigned any = __ballot_sync(0xffffffffu, nz);
        if (tid == 0) sh_is64 = (any == 0u);
    }
    __syncthreads();
    const int is64 = sh_is64;
    const int labbase = b * LM1;

    int mylab[16];
    int lh[8] = {0, 0, 0, 0, 0, 0, 0, 0};
    #pragma unroll
    for (int k = 0; k < 16; k++) {
        int i = tid * 16 + k;
        int l = -1;
        if (i < LM1) {
            int gi = labbase + i;
            l = lab32[is64 ? (2 * gi) : gi];
            lh[l]++;
        }
        mylab[k] = l;
    }
    #pragma unroll
    for (int l = 0; l < 8; l++) cnt[l][tid] = lh[l];
    __syncthreads();

    {
        int w = tid >> 5, lane = tid & 31;
        int carry = 0;
        for (int c = 0; c < 8; c++) {
            int t = c * 32 + lane;
            int v = cnt[w][t];
            int x = v;
            #pragma unroll
            for (int o = 1; o < 32; o <<= 1) {
                int y = __shfl_up_sync(0xffffffffu, x, o);
                if (lane >= o) x += y;
            }
            ex[w][t] = carry + x - v;
            carry += __shfl_sync(0xffffffffu, x, 31);
        }
        if (lane == 0) tot[w] = carry;
    }
    __syncthreads();

    if (tid == 0) {
        int s = 0;
        int nb = 0;
        #pragma unroll
        for (int l = 0; l < 8; l++) {
            segstart[l] = s;
            int e = s + tot[l];
            int kb = s & ~(BN - 1);
            int ke = min((e + BN - 1) & ~(BN - 1), LSEQ);
            for (int q0 = s; q0 < e; q0 += BM) {
                g_btab[b * MAXBLK + nb] = make_int4(q0, e, kb, ke);
                nb++;
            }
            s = e;
        }
        g_nblk[b] = nb;
        g_perm[b * LSEQ + LM1] = LM1;
        g_slab[b * LSEQ + LM1] = -2;
    }
    __syncthreads();

    int run[8] = {0, 0, 0, 0, 0, 0, 0, 0};
    #pragma unroll
    for (int k = 0; k < 16; k++) {
        int l = mylab[k];
        if (l >= 0) {
            int pos = segstart[l] + ex[l][tid] + run[l]++;
            int i = tid * 16 + k;
            g_perm[b * LSEQ + pos] = i;
            g_slab[b * LSEQ + pos] = l;
        }
    }
}

// ---------------------------------------------------------------------------
// Kernel B: gather K/V rows into sorted order (float4 granularity).
// ---------------------------------------------------------------------------
__global__ void gather_kernel(const float* __restrict__ K,
                              const float* __restrict__ V)
{
    int idx = blockIdx.x * blockDim.x + threadIdx.x;
    int r = idx >> 4;
    int c = idx & 15;
    int b = r >> 12;
    int src = g_perm[r];
    long long so = ((long long)(b << 12) + src) * 16 + c;
    ((float4*)g_Ks)[r * 16 + c] = ((const float4*)K)[so];
    ((float4*)g_Vs)[r * 16 + c] = ((const float4*)V)[so];
}

// ---------------------------------------------------------------------------
// Kernel C: main kernel, 256 threads.
//   slot <  nblk          : block-sparse flash attention (4x4 reg tiles)
//   nblk <= slot < nblk+16: one time-query split-softmax chunk (256 keys)
// ---------------------------------------------------------------------------
__global__ __launch_bounds__(NTHREADS, 2)
void clustered_attn_kernel(const float* __restrict__ Q,
                           const float* __restrict__ K,
                           const float* __restrict__ V,
                           float* __restrict__ Out)
{
    extern __shared__ float sm[];

    const int b    = blockIdx.y;
    const int slot = blockIdx.x;
    const int tid  = threadIdx.x;
    const int nblk = g_nblk[b];
    const long long bbase = (long long)b * LSEQ;
    const float scale = 0.125f;

    // ===================== time-query chunk path =====================
    if (slot >= nblk) {
        const int c = slot - nblk;
        if (c >= TQ_NCH) return;

        float* q    = sm;             // [64]
        float* p    = sm + 64;        // [256]
        float* red  = sm + 320;       // [16]
        float* vacc = sm + 336;       // [4][64]

        if (tid < HD) q[tid] = Q[(bbase + LM1) * HD + tid];
        __syncthreads();

        const int j = c * TQ_CHUNKS + tid;
        const float* kr = K + (bbase + j) * HD;
        float dot = 0.0f;
        #pragma unroll
        for (int d = 0; d < HD; d += 4) {
            float4 k4 = *reinterpret_cast<const float4*>(kr + d);
            dot += q[d] * k4.x + q[d + 1] * k4.y + q[d + 2] * k4.z + q[d + 3] * k4.w;
        }
        dot *= scale;

        float m = dot;
        #pragma unroll
        for (int o = 16; o >= 1; o >>= 1)
            m = fmaxf(m, __shfl_xor_sync(0xffffffffu, m, o));
        if ((tid & 31) == 0) red[tid >> 5] = m;
        __syncthreads();
        m = red[0];
        #pragma unroll
        for (int w = 1; w < 8; w++) m = fmaxf(m, red[w]);

        float pv = __expf(dot - m);
        p[tid] = pv;

        float s = pv;
        #pragma unroll
        for (int o = 16; o >= 1; o >>= 1)
            s += __shfl_xor_sync(0xffffffffu, s, o);
        if ((tid & 31) == 0) red[8 + (tid >> 5)] = s;
        __syncthreads();
        s = red[8];
        #pragma unroll
        for (int w = 1; w < 8; w++) s += red[8 + w];

        const int d = tid & 63, h = tid >> 6;
        float a = 0.0f;
        #pragma unroll 8
        for (int jj = h * 64; jj < h * 64 + 64; jj++)
            a += p[jj] * V[(bbase + c * TQ_CHUNKS + jj) * HD + d];
        vacc[h * HD + d] = a;
        __syncthreads();

        float* out = g_tq + (b * TQ_NCH + c) * (HD + 2);
        if (tid < HD)
            out[tid] = vacc[tid] + vacc[HD + tid] + vacc[2 * HD + tid] + vacc[3 * HD + tid];
        else if (tid == HD) { out[HD] = m; out[HD + 1] = s; }
        return;
    }

    // ===================== attention path =====================
    float* Qt = sm;                       // [HD][PAD]
    float* Kt = Qt + HD * PAD;            // [HD][PAD]
    float* Pt = Kt + HD * PAD;            // [BN][PAD]
    float* Vs = Pt + BN * PAD;            // [BN][HD]
    int*   klabs = (int*)(Vs + BN * HD);  // [BN]
    float* kt = (float*)(klabs + BN);     // [HD]
    float* vt = kt + HD;                  // [HD]

    const int4 blk = g_btab[b * MAXBLK + slot];
    const int q0 = blk.x, qe = blk.y, kb = blk.z, ke = blk.w;

    const int tx = tid & 15;
    const int ty = tid >> 4;
    const int* perm = g_perm + b * LSEQ;
    const int* slab = g_slab + b * LSEQ;

    const float* Kb = g_Ks + b * LSEQ * HD;
    const float* Vb = g_Vs + b * LSEQ * HD;

    // ---- Q tile (transposed) directly from original Q via perm
    {
        int r = tid >> 2, h = tid & 3;
        int rr = min(q0 + r, LM1);
        int src = perm[rr];
        const float4* qrow = reinterpret_cast<const float4*>(Q + (bbase + src) * HD) + h * 4;
        #pragma unroll
        for (int k2 = 0; k2 < 4; k2++) {
            float4 v4 = qrow[k2];
            int d = h * 16 + k2 * 4;
            Qt[(d + 0) * PAD + r] = v4.x;
            Qt[(d + 1) * PAD + r] = v4.y;
            Qt[(d + 2) * PAD + r] = v4.z;
            Qt[(d + 3) * PAD + r] = v4.w;
        }
    }
    if (tid < HD) kt[tid] = Kb[LM1 * HD + tid];
    else if (tid < 2 * HD) vt[tid - HD] = Vb[LM1 * HD + (tid - HD)];

    int qlab[4];
    #pragma unroll
    for (int i = 0; i < 4; i++) {
        int r = q0 + ty * 4 + i;
        qlab[i] = (r < qe) ? slab[r] : -3;
    }

    float mrow[4], lrow[4], acc[4][4];
    #pragma unroll
    for (int i = 0; i < 4; i++) {
        mrow[i] = -INFINITY;
        lrow[i] = 0.0f;
        #pragma unroll
        for (int j = 0; j < 4; j++) acc[i][j] = 0.0f;
    }

    for (int n0 = kb; n0 < ke; n0 += BN) {
        __syncthreads();

        // ---- vectorized K/V tile load: 4 threads/row, float4
        {
            int r = tid >> 2, h = tid & 3;
            const float4* krow = reinterpret_cast<const float4*>(Kb + (n0 + r) * HD) + h * 4;
            const float4* vrow = reinterpret_cast<const float4*>(Vb + (n0 + r) * HD) + h * 4;
            #pragma unroll
            for (int k2 = 0; k2 < 4; k2++) {
                float4 k4 = krow[k2];
                int d = h * 16 + k2 * 4;
                Kt[(d + 0) * PAD + r] = k4.x;
                Kt[(d + 1) * PAD + r] = k4.y;
                Kt[(d + 2) * PAD + r] = k4.z;
                Kt[(d + 3) * PAD + r] = k4.w;
                *reinterpret_cast<float4*>(&Vs[r * HD + d]) = vrow[k2];
            }
        }
        if (tid < BN) klabs[tid] = slab[n0 + tid];
        __syncthreads();

        float s[4][4];
        #pragma unroll
        for (int i = 0; i < 4; i++)
            #pragma unroll
            for (int j = 0; j < 4; j++) s[i][j] = 0.0f;

        #pragma unroll 8
        for (int d = 0; d < HD; d++) {
            float a[4], bb[4];
            #pragma unroll
            for (int i = 0; i < 4; i++) a[i]  = Qt[d * PAD + 4 * ty + i];
            #pragma unroll
            for (int j = 0; j < 4; j++) bb[j] = Kt[d * PAD + 4 * tx + j];
            #pragma unroll
            for (int i = 0; i < 4; i++)
                #pragma unroll
                for (int j = 0; j < 4; j++) s[i][j] += a[i] * bb[j];
        }

        int klj[4];
        #pragma unroll
        for (int j = 0; j < 4; j++) klj[j] = klabs[4 * tx + j];

        #pragma unroll
        for (int i = 0; i < 4; i++)
            #pragma unroll
            for (int j = 0; j < 4; j++)
                s[i][j] = (qlab[i] == klj[j]) ? s[i][j] * scale : -INFINITY;

        #pragma unroll
        for (int i = 0; i < 4; i++) {
            float tm = fmaxf(fmaxf(s[i][0], s[i][1]), fmaxf(s[i][2], s[i][3]));
            #pragma unroll
            for (int o = 8; o >= 1; o >>= 1)
                tm = fmaxf(tm, __shfl_xor_sync(0xffffffffu, tm, o));

            float newm = fmaxf(mrow[i], tm);
            float mref = (newm == -INFINITY) ? 0.0f : newm;
            float f = __expf(mrow[i] - mref);

            float rs = 0.0f;
            #pragma unroll
            for (int j = 0; j < 4; j++) {
                float p = __expf(s[i][j] - mref);
                s[i][j] = p;
                rs += p;
            }
            #pragma unroll
            for (int o = 8; o >= 1; o >>= 1)
                rs += __shfl_xor_sync(0xffffffffu, rs, o);

            lrow[i] = lrow[i] * f + rs;
            mrow[i] = newm;
            #pragma unroll
            for (int j = 0; j < 4; j++) acc[i][j] *= f;
        }

        #pragma unroll
        for (int i = 0; i < 4; i++)
            #pragma unroll
            for (int j = 0; j < 4; j++)
                Pt[(4 * tx + j) * PAD + (4 * ty + i)] = s[i][j];
        __syncthreads();

        #pragma unroll 8
        for (int n = 0; n < BN; n++) {
            float a[4], bb[4];
            #pragma unroll
            for (int i = 0; i < 4; i++) a[i]  = Pt[n * PAD + 4 * ty + i];
            #pragma unroll
            for (int j = 0; j < 4; j++) bb[j] = Vs[n * HD + 4 * tx + j];
            #pragma unroll
            for (int i = 0; i < 4; i++)
                #pragma unroll
                for (int j = 0; j < 4; j++) acc[i][j] += a[i] * bb[j];
        }
    }

    // ---- time key column
    #pragma unroll
    for (int i = 0; i < 4; i++) {
        float part = 0.0f;
        #pragma unroll
        for (int jj = 0; jj < 4; jj++)
            part += Qt[(4 * tx + jj) * PAD + (4 * ty + i)] * kt[4 * tx + jj];
        #pragma unroll
        for (int o = 8; o >= 1; o >>= 1)
            part += __shfl_xor_sync(0xffffffffu, part, o);
        float st = part * scale;

        float newm = fmaxf(mrow[i], st);
        float f = __expf(mrow[i] - newm);
        float p = __expf(st - newm);
        lrow[i] = lrow[i] * f + p;
        mrow[i] = newm;
        #pragma unroll
        for (int j = 0; j < 4; j++)
            acc[i][j] = acc[i][j] * f + p * vt[4 * tx + j];
    }

    // ---- epilogue
    #pragma unroll
    for (int i = 0; i < 4; i++) {
        int r = q0 + 4 * ty + i;
        if (r < qe) {
            float inv = 1.0f / lrow[i];
            int orig = perm[r];
            float4 o4;
            o4.x = acc[i][0] * inv;
            o4.y = acc[i][1] * inv;
            o4.z = acc[i][2] * inv;
            o4.w = acc[i][3] * inv;
            *reinterpret_cast<float4*>(&Out[(bbase + orig) * HD + 4 * tx]) = o4;
        }
    }
}

// ---------------------------------------------------------------------------
// Kernel D: combine time-query partials. Grid = B, 64 threads.
// Parallel-staged (m,s), 4-way split accumulation for MLP.
// ---------------------------------------------------------------------------
__global__ void timeq_combine(float* __restrict__ Out)
{
    __shared__ float ms[TQ_NCH], ss[TQ_NCH];
    const int b = blockIdx.x;
    const int tid = threadIdx.x;
    const float* part = g_tq + b * TQ_NCH * (HD + 2);

    if (tid < TQ_NCH) {
        ms[tid] = part[tid * (HD + 2) + HD];
        ss[tid] = part[tid * (HD + 2) + HD + 1];
    }
    __syncthreads();

    float M = ms[0];
    #pragma unroll
    for (int c = 1; c < TQ_NCH; c++) M = fmaxf(M, ms[c]);

    float f[TQ_NCH];
    float stot = 0.0f;
    #pragma unroll
    for (int c = 0; c < TQ_NCH; c++) {
        f[c] = __expf(ms[c] - M);
        stot += ss[c] * f[c];
    }

    // 4 independent partial sums -> 4+ loads in flight
    float a0 = 0.0f, a1 = 0.0f, a2 = 0.0f, a3 = 0.0f;
    #pragma unroll
    for (int c = 0; c < TQ_NCH; c += 4) {
        a0 += part[(c + 0) * (HD + 2) + tid] * f[c + 0];
        a1 += part[(c + 1) * (HD + 2) + tid] * f[c + 1];
        a2 += part[(c + 2) * (HD + 2) + tid] * f[c + 2];
        a3 += part[(c + 3) * (HD + 2) + tid] * f[c + 3];
    }
    float a = (a0 + a1) + (a2 + a3);
    Out[((long long)b * LSEQ + LM1) * HD + tid] = a / stot;
}

// ---------------------------------------------------------------------------
extern "C" void kernel_launch(void* const* d_in, const int* in_sizes, int n_in,
                              void* d_out, int out_size)
{
    const float* Q = (const float*)d_in[0];
    const float* K = (const float*)d_in[1];
    const float* V = (const float*)d_in[2];
    const int* lab = (const int*)d_in[3];
    float* Out = (float*)d_out;

    const int B = in_sizes[0] / (LSEQ * HD);

    sort_kernel<<<B, 256>>>(lab);
    gather_kernel<<<B * 256, 256>>>(K, V);

    const int smem_bytes = (HD * PAD * 2 + BN * PAD + BN * HD + 2 * HD) * (int)sizeof(float)
                           + BN * (int)sizeof(int);
    cudaFuncSetAttribute(clustered_attn_kernel,
                         cudaFuncAttributeMaxDynamicSharedMemorySize, smem_bytes);
    dim3 grid(GRIDX, B);
    clustered_attn_kernel<<<grid, NTHREADS, smem_bytes>>>(Q, K, V, Out);

    timeq_combine<<<B, HD>>>(Out);
}

// round 9
// speedup vs baseline: 1.1448x; 1.1448x over previous
#include <cuda_runtime.h>
#include <math.h>

// ClusteredAttention: b=4, l=4096, d=64 fp32, labels in [0,8).
// Counting-sort by label -> perm/slab/block-table; gather K/V cluster-
// contiguous; flash-attend cluster-aligned 64-query blocks (256 thr, 4x4
// register tiles computed with packed fma.rn.f32x2 -> half the FFMA and LDS
// issue). Time-query split-softmax chunks absorbed into spare grid slots;
// combine fused into the last chunk block via threadfence+atomic counter.

#define LSEQ 4096
#define LM1  4095
#define HD   64
#define BM   64
#define BN   64
#define PADQ 66          // even -> 8B-aligned LDS.64 on Qt/Kt/Pt rows
#define NTHREADS 256
#define MAXB 4
#define MAXBLK 72
#define TQ_CHUNKS 256
#define TQ_NCH    (LSEQ / TQ_CHUNKS)   // 16
#define GRIDX     (MAXBLK + TQ_NCH)    // 88

__device__ float g_Ks[MAXB * LSEQ * HD];
__device__ float g_Vs[MAXB * LSEQ * HD];
__device__ int   g_perm[MAXB * LSEQ];
__device__ int   g_slab[MAXB * LSEQ];
__device__ int4  g_btab[MAXB * MAXBLK];
__device__ int   g_nblk[MAXB];
__device__ float g_tq[MAXB * TQ_NCH * (HD + 2)];
__device__ int   g_tqcnt[MAXB];

typedef unsigned long long u64t;

__device__ __forceinline__ u64t pack2(float lo, float hi) {
    u64t r;
    asm("mov.b64 %0, {%1, %2};" : "=l"(r) : "f"(lo), "f"(hi));
    return r;
}
__device__ __forceinline__ void unpack2(u64t v, float& lo, float& hi) {
    asm("mov.b64 {%0, %1}, %2;" : "=f"(lo), "=f"(hi) : "l"(v));
}
__device__ __forceinline__ u64t ffma2(u64t a, u64t b, u64t c) {
    u64t d;
    asm("fma.rn.f32x2 %0, %1, %2, %3;" : "=l"(d) : "l"(a), "l"(b), "l"(c));
    return d;
}
__device__ __forceinline__ u64t fmul2(u64t a, u64t b) {
    u64t d;
    asm("mul.rn.f32x2 %0, %1, %2;" : "=l"(d) : "l"(a), "l"(b));
    return d;
}

// ---------------------------------------------------------------------------
// Kernel A: stable counting sort by label + cluster-aligned block table.
// ---------------------------------------------------------------------------
__global__ void sort_kernel(const int* __restrict__ lab32)
{
    __shared__ int cnt[8][256];
    __shared__ int ex[8][256];
    __shared__ int tot[8];
    __shared__ int segstart[8];
    __shared__ int sh_is64;

    const int b = blockIdx.x;
    const int tid = threadIdx.x;

    // parallel int64-vs-int32 autodetect: one load per lane + ballot
    if (tid < 32) {
        int nz = (lab32[2 * tid + 1] != 0) ? 1 : 0;
        unsigned any = __ballot_sync(0xffffffffu, nz);
        if (tid == 0) { sh_is64 = (any == 0u); g_tqcnt[b] = 0; }
    }
    __syncthreads();
    const int is64 = sh_is64;
    const int labbase = b * LM1;

    int mylab[16];
    int lh[8] = {0, 0, 0, 0, 0, 0, 0, 0};
    #pragma unroll
    for (int k = 0; k < 16; k++) {
        int i = tid * 16 + k;
        int l = -1;
        if (i < LM1) {
            int gi = labbase + i;
            l = lab32[is64 ? (2 * gi) : gi];
            lh[l]++;
        }
        mylab[k] = l;
    }
    #pragma unroll
    for (int l = 0; l < 8; l++) cnt[l][tid] = lh[l];
    __syncthreads();

    {
        int w = tid >> 5, lane = tid & 31;
        int carry = 0;
        for (int c = 0; c < 8; c++) {
            int t = c * 32 + lane;
            int v = cnt[w][t];
            int x = v;
            #pragma unroll
            for (int o = 1; o < 32; o <<= 1) {
                int y = __shfl_up_sync(0xffffffffu, x, o);
                if (lane >= o) x += y;
            }
            ex[w][t] = carry + x - v;
            carry += __shfl_sync(0xffffffffu, x, 31);
        }
        if (lane == 0) tot[w] = carry;
    }
    __syncthreads();

    if (tid == 0) {
        int s = 0;
        int nb = 0;
        #pragma unroll
        for (int l = 0; l < 8; l++) {
            segstart[l] = s;
            int e = s + tot[l];
            int kb = s & ~(BN - 1);
            int ke = min((e + BN - 1) & ~(BN - 1), LSEQ);
            for (int q0 = s; q0 < e; q0 += BM) {
                g_btab[b * MAXBLK + nb] = make_int4(q0, e, kb, ke);
                nb++;
            }
            s = e;
        }
        g_nblk[b] = nb;
        g_perm[b * LSEQ + LM1] = LM1;
        g_slab[b * LSEQ + LM1] = -2;
    }
    __syncthreads();

    int run[8] = {0, 0, 0, 0, 0, 0, 0, 0};
    #pragma unroll
    for (int k = 0; k < 16; k++) {
        int l = mylab[k];
        if (l >= 0) {
            int pos = segstart[l] + ex[l][tid] + run[l]++;
            int i = tid * 16 + k;
            g_perm[b * LSEQ + pos] = i;
            g_slab[b * LSEQ + pos] = l;
        }
    }
}

// ---------------------------------------------------------------------------
// Kernel B: gather K/V rows into sorted order (float4 granularity).
// ---------------------------------------------------------------------------
__global__ void gather_kernel(const float* __restrict__ K,
                              const float* __restrict__ V)
{
    int idx = blockIdx.x * blockDim.x + threadIdx.x;
    int r = idx >> 4;
    int c = idx & 15;
    int b = r >> 12;
    int src = g_perm[r];
    long long so = ((long long)(b << 12) + src) * 16 + c;
    ((float4*)g_Ks)[r * 16 + c] = ((const float4*)K)[so];
    ((float4*)g_Vs)[r * 16 + c] = ((const float4*)V)[so];
}

// ---------------------------------------------------------------------------
// Kernel C: main kernel, 256 threads.
//   slot <  nblk          : block-sparse flash attention (f32x2 GEMMs)
//   nblk <= slot < nblk+16: one time-query chunk; last chunk also combines
// ---------------------------------------------------------------------------
__global__ __launch_bounds__(NTHREADS, 2)
void clustered_attn_kernel(const float* __restrict__ Q,
                           const float* __restrict__ K,
                           const float* __restrict__ V,
                           float* __restrict__ Out)
{
    extern __shared__ float sm[];

    const int b    = blockIdx.y;
    const int slot = blockIdx.x;
    const int tid  = threadIdx.x;
    const int nblk = g_nblk[b];
    const long long bbase = (long long)b * LSEQ;
    const float scale = 0.125f;

    // ===================== time-query chunk path =====================
    if (slot >= nblk) {
        const int c = slot - nblk;
        if (c >= TQ_NCH) return;

        float* q    = sm;             // [64]
        float* p    = sm + 64;        // [256]
        float* red  = sm + 320;       // [16]
        float* vacc = sm + 336;       // [4][64]
        __shared__ int amlast;

        if (tid < HD) q[tid] = Q[(bbase + LM1) * HD + tid];
        __syncthreads();

        const int j = c * TQ_CHUNKS + tid;
        const float* kr = K + (bbase + j) * HD;
        float dot = 0.0f;
        #pragma unroll
        for (int d = 0; d < HD; d += 4) {
            float4 k4 = *reinterpret_cast<const float4*>(kr + d);
            dot += q[d] * k4.x + q[d + 1] * k4.y + q[d + 2] * k4.z + q[d + 3] * k4.w;
        }
        dot *= scale;

        float m = dot;
        #pragma unroll
        for (int o = 16; o >= 1; o >>= 1)
            m = fmaxf(m, __shfl_xor_sync(0xffffffffu, m, o));
        if ((tid & 31) == 0) red[tid >> 5] = m;
        __syncthreads();
        m = red[0];
        #pragma unroll
        for (int w = 1; w < 8; w++) m = fmaxf(m, red[w]);

        float pv = __expf(dot - m);
        p[tid] = pv;

        float s = pv;
        #pragma unroll
        for (int o = 16; o >= 1; o >>= 1)
            s += __shfl_xor_sync(0xffffffffu, s, o);
        if ((tid & 31) == 0) red[8 + (tid >> 5)] = s;
        __syncthreads();
        s = red[8];
        #pragma unroll
        for (int w = 1; w < 8; w++) s += red[8 + w];

        const int d = tid & 63, h = tid >> 6;
        float a = 0.0f;
        #pragma unroll 8
        for (int jj = h * 64; jj < h * 64 + 64; jj++)
            a += p[jj] * V[(bbase + c * TQ_CHUNKS + jj) * HD + d];
        vacc[h * HD + d] = a;
        __syncthreads();

        float* out = g_tq + (b * TQ_NCH + c) * (HD + 2);
        if (tid < HD)
            out[tid] = vacc[tid] + vacc[HD + tid] + vacc[2 * HD + tid] + vacc[3 * HD + tid];
        else if (tid == HD) { out[HD] = m; out[HD + 1] = s; }
        __syncthreads();

        // ---- last chunk of this batch performs the combine
        __threadfence();
        if (tid == 0) amlast = (atomicAdd(&g_tqcnt[b], 1) == TQ_NCH - 1);
        __syncthreads();
        if (!amlast) return;
        __threadfence();

        if (tid < HD) {
            const float* part = g_tq + b * TQ_NCH * (HD + 2);
            float M = -INFINITY;
            #pragma unroll
            for (int cc = 0; cc < TQ_NCH; cc++)
                M = fmaxf(M, part[cc * (HD + 2) + HD]);
            float stot = 0.0f, a2 = 0.0f;
            #pragma unroll
            for (int cc = 0; cc < TQ_NCH; cc++) {
                float f = __expf(part[cc * (HD + 2) + HD] - M);
                stot += part[cc * (HD + 2) + HD + 1] * f;
                a2   += part[cc * (HD + 2) + tid] * f;
            }
            Out[(bbase + LM1) * HD + tid] = a2 / stot;
        }
        return;
    }

    // ===================== attention path =====================
    float* Qt = sm;                       // [HD][PADQ]
    float* Kt = Qt + HD * PADQ;           // [HD][PADQ]
    float* Pt = Kt + HD * PADQ;           // [BN][PADQ]
    float* Vs = Pt + BN * PADQ;           // [BN][HD]
    int*   klabs = (int*)(Vs + BN * HD);  // [BN]
    float* kt = (float*)(klabs + BN);     // [HD]
    float* vt = kt + HD;                  // [HD]

    const int4 blk = g_btab[b * MAXBLK + slot];
    const int q0 = blk.x, qe = blk.y, kb = blk.z, ke = blk.w;

    const int tx = tid & 15;
    const int ty = tid >> 4;
    const int* perm = g_perm + b * LSEQ;
    const int* slab = g_slab + b * LSEQ;

    const float* Kb = g_Ks + b * LSEQ * HD;
    const float* Vb = g_Vs + b * LSEQ * HD;

    // ---- Q tile (transposed) directly from original Q via perm
    {
        int r = tid >> 2, h = tid & 3;
        int rr = min(q0 + r, LM1);
        int src = perm[rr];
        const float4* qrow = reinterpret_cast<const float4*>(Q + (bbase + src) * HD) + h * 4;
        #pragma unroll
        for (int k2 = 0; k2 < 4; k2++) {
            float4 v4 = qrow[k2];
            int d = h * 16 + k2 * 4;
            Qt[(d + 0) * PADQ + r] = v4.x;
            Qt[(d + 1) * PADQ + r] = v4.y;
            Qt[(d + 2) * PADQ + r] = v4.z;
            Qt[(d + 3) * PADQ + r] = v4.w;
        }
    }
    if (tid < HD) kt[tid] = Kb[LM1 * HD + tid];
    else if (tid < 2 * HD) vt[tid - HD] = Vb[LM1 * HD + (tid - HD)];

    int qlab[4];
    #pragma unroll
    for (int i = 0; i < 4; i++) {
        int r = q0 + ty * 4 + i;
        qlab[i] = (r < qe) ? slab[r] : -3;
    }

    float mrow[4], lrow[4];
    u64t acc2[2][4];                    // lanes: (i=2ip, i=2ip+1), col j
    #pragma unroll
    for (int i = 0; i < 4; i++) { mrow[i] = -INFINITY; lrow[i] = 0.0f; }
    #pragma unroll
    for (int ip = 0; ip < 2; ip++)
        #pragma unroll
        for (int j = 0; j < 4; j++) acc2[ip][j] = 0ull;

    for (int n0 = kb; n0 < ke; n0 += BN) {
        __syncthreads();

        // ---- scalar coalesced K/V tile load (proven)
        #pragma unroll
        for (int idx = tid; idx < BN * HD; idx += NTHREADS) {
            int n = idx >> 6, d = idx & 63;
            Kt[d * PADQ + n] = Kb[(n0 + n) * HD + d];
            Vs[n * HD + d]  = Vb[(n0 + n) * HD + d];
        }
        if (tid < BN) klabs[tid] = slab[n0 + tid];
        __syncthreads();

        // ---- S = Q K^T : packed f32x2, acc lanes along query-row pairs
        u64t s2[2][4];
        #pragma unroll
        for (int ip = 0; ip < 2; ip++)
            #pragma unroll
            for (int j = 0; j < 4; j++) s2[ip][j] = 0ull;

        #pragma unroll 4
        for (int d = 0; d < HD; d++) {
            u64t a01 = *reinterpret_cast<const u64t*>(&Qt[d * PADQ + 4 * ty]);
            u64t a23 = *reinterpret_cast<const u64t*>(&Qt[d * PADQ + 4 * ty + 2]);
            float2 bl = *reinterpret_cast<const float2*>(&Kt[d * PADQ + 4 * tx]);
            float2 bh = *reinterpret_cast<const float2*>(&Kt[d * PADQ + 4 * tx + 2]);
            u64t bb0 = pack2(bl.x, bl.x);
            u64t bb1 = pack2(bl.y, bl.y);
            u64t bb2 = pack2(bh.x, bh.x);
            u64t bb3 = pack2(bh.y, bh.y);
            s2[0][0] = ffma2(a01, bb0, s2[0][0]);
            s2[0][1] = ffma2(a01, bb1, s2[0][1]);
            s2[0][2] = ffma2(a01, bb2, s2[0][2]);
            s2[0][3] = ffma2(a01, bb3, s2[0][3]);
            s2[1][0] = ffma2(a23, bb0, s2[1][0]);
            s2[1][1] = ffma2(a23, bb1, s2[1][1]);
            s2[1][2] = ffma2(a23, bb2, s2[1][2]);
            s2[1][3] = ffma2(a23, bb3, s2[1][3]);
        }

        // ---- unpack to scalars for mask + softmax
        float s[4][4];
        #pragma unroll
        for (int ip = 0; ip < 2; ip++)
            #pragma unroll
            for (int j = 0; j < 4; j++)
                unpack2(s2[ip][j], s[2 * ip][j], s[2 * ip + 1][j]);

        int klj[4];
        #pragma unroll
        for (int j = 0; j < 4; j++) klj[j] = klabs[4 * tx + j];

        #pragma unroll
        for (int i = 0; i < 4; i++)
            #pragma unroll
            for (int j = 0; j < 4; j++)
                s[i][j] = (qlab[i] == klj[j]) ? s[i][j] * scale : -INFINITY;

        float fi[4];
        #pragma unroll
        for (int i = 0; i < 4; i++) {
            float tm = fmaxf(fmaxf(s[i][0], s[i][1]), fmaxf(s[i][2], s[i][3]));
            #pragma unroll
            for (int o = 8; o >= 1; o >>= 1)
                tm = fmaxf(tm, __shfl_xor_sync(0xffffffffu, tm, o));

            float newm = fmaxf(mrow[i], tm);
            float mref = (newm == -INFINITY) ? 0.0f : newm;
            fi[i] = __expf(mrow[i] - mref);

            float rs = 0.0f;
            #pragma unroll
            for (int j = 0; j < 4; j++) {
                float p = __expf(s[i][j] - mref);
                s[i][j] = p;
                rs += p;
            }
            #pragma unroll
            for (int o = 8; o >= 1; o >>= 1)
                rs += __shfl_xor_sync(0xffffffffu, rs, o);

            lrow[i] = lrow[i] * fi[i] + rs;
            mrow[i] = newm;
        }

        // packed accumulator rescale
        {
            u64t ff0 = pack2(fi[0], fi[1]);
            u64t ff1 = pack2(fi[2], fi[3]);
            #pragma unroll
            for (int j = 0; j < 4; j++) {
                acc2[0][j] = fmul2(acc2[0][j], ff0);
                acc2[1][j] = fmul2(acc2[1][j], ff1);
            }
        }

        // ---- stage P^T, then O += P @ V (packed)
        #pragma unroll
        for (int i = 0; i < 4; i++)
            #pragma unroll
            for (int j = 0; j < 4; j++)
                Pt[(4 * tx + j) * PADQ + (4 * ty + i)] = s[i][j];
        __syncthreads();

        #pragma unroll 4
        for (int n = 0; n < BN; n++) {
            u64t a01 = *reinterpret_cast<const u64t*>(&Pt[n * PADQ + 4 * ty]);
            u64t a23 = *reinterpret_cast<const u64t*>(&Pt[n * PADQ + 4 * ty + 2]);
            float2 vl = *reinterpret_cast<const float2*>(&Vs[n * HD + 4 * tx]);
            float2 vh = *reinterpret_cast<const float2*>(&Vs[n * HD + 4 * tx + 2]);
            u64t vb0 = pack2(vl.x, vl.x);
            u64t vb1 = pack2(vl.y, vl.y);
            u64t vb2 = pack2(vh.x, vh.x);
            u64t vb3 = pack2(vh.y, vh.y);
            acc2[0][0] = ffma2(a01, vb0, acc2[0][0]);
            acc2[0][1] = ffma2(a01, vb1, acc2[0][1]);
            acc2[0][2] = ffma2(a01, vb2, acc2[0][2]);
            acc2[0][3] = ffma2(a01, vb3, acc2[0][3]);
            acc2[1][0] = ffma2(a23, vb0, acc2[1][0]);
            acc2[1][1] = ffma2(a23, vb1, acc2[1][1]);
            acc2[1][2] = ffma2(a23, vb2, acc2[1][2]);
            acc2[1][3] = ffma2(a23, vb3, acc2[1][3]);
        }
    }

    // ---- unpack accumulators
    float acc[4][4];
    #pragma unroll
    for (int ip = 0; ip < 2; ip++)
        #pragma unroll
        for (int j = 0; j < 4; j++)
            unpack2(acc2[ip][j], acc[2 * ip][j], acc[2 * ip + 1][j]);

    // ---- time key column (every real query attends to it)
    #pragma unroll
    for (int i = 0; i < 4; i++) {
        float part = 0.0f;
        #pragma unroll
        for (int jj = 0; jj < 4; jj++)
            part += Qt[(4 * tx + jj) * PADQ + (4 * ty + i)] * kt[4 * tx + jj];
        #pragma unroll
        for (int o = 8; o >= 1; o >>= 1)
            part += __shfl_xor_sync(0xffffffffu, part, o);
        float st = part * scale;

        float newm = fmaxf(mrow[i], st);
        float f = __expf(mrow[i] - newm);
        float p = __expf(st - newm);
        lrow[i] = lrow[i] * f + p;
        mrow[i] = newm;
        #pragma unroll
        for (int j = 0; j < 4; j++)
            acc[i][j] = acc[i][j] * f + p * vt[4 * tx + j];
    }

    // ---- epilogue: normalize + scatter
    #pragma unroll
    for (int i = 0; i < 4; i++) {
        int r = q0 + 4 * ty + i;
        if (r < qe) {
            float inv = 1.0f / lrow[i];
            int orig = perm[r];
            float4 o4;
            o4.x = acc[i][0] * inv;
            o4.y = acc[i][1] * inv;
            o4.z = acc[i][2] * inv;
            o4.w = acc[i][3] * inv;
            *reinterpret_cast<float4*>(&Out[(bbase + orig) * HD + 4 * tx]) = o4;
        }
    }
}

// ---------------------------------------------------------------------------
extern "C" void kernel_launch(void* const* d_in, const int* in_sizes, int n_in,
                              void* d_out, int out_size)
{
    const float* Q = (const float*)d_in[0];
    const float* K = (const float*)d_in[1];
    const float* V = (const float*)d_in[2];
    const int* lab = (const int*)d_in[3];
    float* Out = (float*)d_out;

    const int B = in_sizes[0] / (LSEQ * HD);

    sort_kernel<<<B, 256>>>(lab);
    gather_kernel<<<B * 256, 256>>>(K, V);

    const int smem_bytes = (HD * PADQ * 2 + BN * PADQ + BN * HD + 2 * HD) * (int)sizeof(float)
                           + BN * (int)sizeof(int);
    cudaFuncSetAttribute(clustered_attn_kernel,
                         cudaFuncAttributeMaxDynamicSharedMemorySize, smem_bytes);
    dim3 grid(GRIDX, B);
    clustered_attn_kernel<<<grid, NTHREADS, smem_bytes>>>(Q, K, V, Out);
}